// round 17
// baseline (speedup 1.0000x reference)
#include <cuda_runtime.h>
#include <math.h>
#include <stdint.h>

#define NP 36864          // 192*192 output pixels
#define WOUT 192
#define HIN 96

// ---------------- static scratch (no allocations allowed) ----------------
__device__ float g_a[128 * NP];         // stage-1 activations: dw half0, pw half1
__device__ float g_b[512 * NP];         // stage-2: dw half0 (256), pw half1 (256)
__device__ float g_dw[576 * NP];
__device__ float g_pw[192 * NP];
__device__ float g_mean[2 * 64 * NP];
__device__ float g_s1[2 * 64 * NP];
__device__ float g_s2[2 * 64 * NP];
__device__ float g_sigma[2 * 2 * NP];
__device__ float g_xa[2 * 64 * NP];
__device__ float g_wr[303104];          // tf32-rounded weights arena

#define WOFF_DW2  0         // 16384
#define WOFF_DW3  16384     // 147456
#define WOFF_PW2  163840    // 16384
#define WOFF_PW3  180224    // 49152
#define WOFF_SIG1 229376    // 36864
#define WOFF_SIG2 266240    // 36864

#define BUF_A     0
#define BUF_B     1
#define BUF_DW    2
#define BUF_PW    3
#define BUF_MEAN  4
#define BUF_S1    5
#define BUF_S2    6
#define BUF_SIGMA 7
#define BUF_XA    8

__device__ __forceinline__ float* buf_ptr(int sel) {
    switch (sel) {
        case BUF_A:     return g_a;
        case BUF_B:     return g_b;
        case BUF_DW:    return g_dw;
        case BUF_PW:    return g_pw;
        case BUF_MEAN:  return g_mean;
        case BUF_S1:    return g_s1;
        case BUF_S2:    return g_s2;
        case BUF_SIGMA: return g_sigma;
        default:        return g_xa;
    }
}

// ---------------- tf32 / mma / cp.async helpers --------------------------
__device__ __forceinline__ float to_tf32(float x) {
    uint32_t o;
    asm("cvt.rna.tf32.f32 %0, %1;" : "=r"(o) : "f"(x));
    return __uint_as_float(o);
}
__device__ __forceinline__ void mma_tf32(float* d, const uint32_t* a, const uint32_t* b) {
    asm volatile(
        "mma.sync.aligned.m16n8k8.row.col.f32.tf32.tf32.f32 "
        "{%0,%1,%2,%3}, {%4,%5,%6,%7}, {%8,%9}, {%0,%1,%2,%3};"
        : "+f"(d[0]), "+f"(d[1]), "+f"(d[2]), "+f"(d[3])
        : "r"(a[0]), "r"(a[1]), "r"(a[2]), "r"(a[3]), "r"(b[0]), "r"(b[1]));
}
__device__ __forceinline__ void cp16(float* dst_smem, const float* src, bool pred) {
    uint32_t d = (uint32_t)__cvta_generic_to_shared(dst_smem);
    int sz = pred ? 16 : 0;
    asm volatile("cp.async.cg.shared.global [%0], [%1], 16, %2;"
                 :: "r"(d), "l"(src), "r"(sz));
}
__device__ __forceinline__ void cp4(float* dst_smem, const float* src, bool pred) {
    uint32_t d = (uint32_t)__cvta_generic_to_shared(dst_smem);
    int sz = pred ? 4 : 0;
    asm volatile("cp.async.ca.shared.global [%0], [%1], 4, %2;"
                 :: "r"(d), "l"(src), "r"(sz));
}
#define CP_COMMIT() asm volatile("cp.async.commit_group;" ::: "memory")
template<int N> __device__ __forceinline__ void cp_wait() {
    asm volatile("cp.async.wait_group %0;" :: "n"(N) : "memory");
}

// ---------------- weight pre-rounding (fused) ----------------
__global__ void k_round4(const float* __restrict__ w0, const float* __restrict__ w1,
                         const float* __restrict__ w2, const float* __restrict__ w3) {
    int i = blockIdx.x * 256 + threadIdx.x;
    if (i < 16384)       g_wr[i] = to_tf32(w0[i]);
    else if (i < 163840) g_wr[i] = to_tf32(w1[i - 16384]);
    else if (i < 180224) g_wr[i] = to_tf32(w2[i - 163840]);
    else if (i < 229376) g_wr[i] = to_tf32(w3[i - 180224]);
}
__global__ void k_round2(const float* __restrict__ w0, const float* __restrict__ w1) {
    int i = blockIdx.x * 256 + threadIdx.x;
    if (i < 36864)      g_wr[WOFF_SIG1 + i] = to_tf32(w0[i]);
    else if (i < 73728) g_wr[WOFF_SIG2 + i - 36864] = to_tf32(w1[i - 36864]);
}

// ---------------- 1x1 conv as tf32 GEMM, warp tile 64x64, BK=8 -----------
// 128 threads / 4 warps (2m x 2n), CTA tile 128x128, cp.async depth-2.
template<bool RELU, bool ROUND>
__global__ void __launch_bounds__(128)
k_gemm_mma(int woff, const float* __restrict__ bias, int src, int xch,
           int dst, int ych, int OC, int IC) {
    const float* __restrict__ W = g_wr + woff;
    const float* __restrict__ X = buf_ptr(src) + (size_t)xch * NP;
    float* __restrict__ Y = buf_ptr(dst) + (size_t)ych * NP;

    __shared__ __align__(16) float sA[2][128 * 12];   // [m][k], pitch 12
    __shared__ __align__(16) float sB[2][8 * 136];    // [k][n], pitch 136

    const int tid  = threadIdx.x;
    const int lane = tid & 31, wid = tid >> 5;
    const int m0 = blockIdx.y * 128, n0 = blockIdx.x * 128;
    const int wm = (wid & 1) * 64;
    const int wn = (wid >> 1) * 64;
    const int nch = IC >> 3;

    float acc[4][8][4];
#pragma unroll
    for (int i = 0; i < 4; i++)
#pragma unroll
        for (int j = 0; j < 8; j++)
#pragma unroll
            for (int r = 0; r < 4; r++) acc[i][j][r] = 0.f;

    auto issue = [&](int t) {
        float* dA = sA[t & 1];
        float* dB = sB[t & 1];
        const int k0 = t * 8;
#pragma unroll
        for (int i = 0; i < 2; i++) {
            int e = tid + i * 128;          // 0..255
            int r = e >> 1, c = e & 1;
            cp16(dA + r * 12 + c * 4, W + (size_t)(m0 + r) * IC + k0 + c * 4,
                 m0 + r < OC);
        }
#pragma unroll
        for (int i = 0; i < 2; i++) {
            int e = tid + i * 128;
            int r = e >> 5, c = e & 31;
            cp16(dB + r * 136 + c * 4, X + (size_t)(k0 + r) * NP + n0 + c * 4, true);
        }
        CP_COMMIT();
    };

    issue(0);
    if (nch > 1) issue(1);

    for (int t = 0; t < nch; t++) {
        if (t < nch - 1) cp_wait<1>(); else cp_wait<0>();
        __syncthreads();
        const float* cA = sA[t & 1];
        const float* cB = sB[t & 1];
        uint32_t a[4][4], b[8][2];
#pragma unroll
        for (int i = 0; i < 4; i++) {
            const float* base = cA + (wm + i * 16 + (lane >> 2)) * 12 + (lane & 3);
            a[i][0] = __float_as_uint(base[0]);
            a[i][1] = __float_as_uint(base[8 * 12]);
            a[i][2] = __float_as_uint(base[4]);
            a[i][3] = __float_as_uint(base[8 * 12 + 4]);
        }
#pragma unroll
        for (int j = 0; j < 8; j++) {
            const float* base = cB + (lane & 3) * 136 + wn + j * 8 + (lane >> 2);
            b[j][0] = __float_as_uint(base[0]);
            b[j][1] = __float_as_uint(base[4 * 136]);
        }
#pragma unroll
        for (int i = 0; i < 4; i++)
#pragma unroll
            for (int j = 0; j < 8; j++)
                mma_tf32(acc[i][j], a[i], b[j]);
        __syncthreads();
        if (t + 2 < nch) issue(t + 2);
    }

#pragma unroll
    for (int i = 0; i < 4; i++) {
#pragma unroll
        for (int half = 0; half < 2; half++) {
            int oc = m0 + wm + i * 16 + (lane >> 2) + half * 8;
            if (oc < OC) {
                float bb = bias[oc];
#pragma unroll
                for (int j = 0; j < 8; j++) {
                    int col = n0 + wn + j * 8 + (lane & 3) * 2;
                    float v0 = acc[i][j][half * 2 + 0] + bb;
                    float v1 = acc[i][j][half * 2 + 1] + bb;
                    if (RELU) { v0 = fmaxf(v0, 0.f); v1 = fmaxf(v1, 0.f); }
                    if (ROUND) { v0 = to_tf32(v0); v1 = to_tf32(v1); }
                    *reinterpret_cast<float2*>(Y + (size_t)oc * NP + col) =
                        make_float2(v0, v1);
                }
            }
        }
    }
}

// ---------------- 3x3 conv (64->64) implicit GEMM, depth-3 pipeline ------
template<int SRC, int DST, bool RELU, bool ROUND>
__global__ void __launch_bounds__(256)
k_conv_mma(int woff, const float* __restrict__ bias) {
    const float* __restrict__ Wt = g_wr + woff;
    const float* __restrict__ in = buf_ptr(SRC);
    float* __restrict__ out = buf_ptr(DST);

    __shared__ __align__(16) float sA[3][64 * 20];
    __shared__ __align__(16) float sB[3][16 * 136];

    const int tid  = threadIdx.x;
    const int lane = tid & 31, wid = tid >> 5;
    const int q0 = blockIdx.x * 128;
    const int b  = q0 / NP;
    const int p0 = q0 - b * NP;
    const float* __restrict__ inb = in + (size_t)b * 64 * NP;
    const int wm = (wid & 1) * 32;
    const int wn = (wid >> 1) * 32;
    const int NST = 36;

    float acc[2][4][4];
#pragma unroll
    for (int i = 0; i < 2; i++)
#pragma unroll
        for (int j = 0; j < 4; j++)
#pragma unroll
            for (int r = 0; r < 4; r++) acc[i][j][r] = 0.f;

    auto issue = [&](int s) {
        const int tap = s >> 2, icc = (s & 3) * 16;
        const int ky = tap / 3, kx = tap - ky * 3;
        const int off = (ky - 1) * WOUT + (kx - 1);
        float* dA = sA[s % 3];
        float* dB = sB[s % 3];
#pragma unroll
        for (int i = 0; i < 4; i++) {
            int e = tid + i * 256;
            int r = e >> 4, c = e & 15;
            cp4(dA + r * 20 + c, Wt + ((size_t)r * 64 + icc + c) * 9 + tap, true);
        }
#pragma unroll
        for (int i = 0; i < 8; i++) {
            int e = tid + i * 256;
            int r = e >> 7, c = e & 127;
            int p = p0 + c;
            int y = p / WOUT, x = p - y * WOUT;
            int gy = y + ky - 1, gx = x + kx - 1;
            bool ok = (gy >= 0) && (gy < WOUT) && (gx >= 0) && (gx < WOUT);
            cp4(dB + r * 136 + c, inb + (size_t)(icc + r) * NP + p + off, ok);
        }
        CP_COMMIT();
    };

    issue(0);
    issue(1);

    for (int s = 0; s < NST; s++) {
        if (s + 2 < NST) { issue(s + 2); cp_wait<2>(); }
        else if (s + 1 < NST) cp_wait<1>();
        else cp_wait<0>();
        __syncthreads();
        const float* cA = sA[s % 3];
        const float* cB = sB[s % 3];
#pragma unroll
        for (int ks = 0; ks < 2; ks++) {
            const int kk = ks * 8;
            uint32_t a[2][4], bf[4][2];
#pragma unroll
            for (int i = 0; i < 2; i++) {
                const float* base = cA + (wm + i * 16 + (lane >> 2)) * 20 + kk + (lane & 3);
                a[i][0] = __float_as_uint(base[0]);
                a[i][1] = __float_as_uint(base[8 * 20]);
                a[i][2] = __float_as_uint(base[4]);
                a[i][3] = __float_as_uint(base[8 * 20 + 4]);
            }
#pragma unroll
            for (int j = 0; j < 4; j++) {
                const float* base = cB + (kk + (lane & 3)) * 136 + wn + j * 8 + (lane >> 2);
                bf[j][0] = __float_as_uint(base[0]);
                bf[j][1] = __float_as_uint(base[4 * 136]);
            }
#pragma unroll
            for (int i = 0; i < 2; i++)
#pragma unroll
                for (int j = 0; j < 4; j++)
                    mma_tf32(acc[i][j], a[i], bf[j]);
        }
        __syncthreads();
    }

#pragma unroll
    for (int i = 0; i < 2; i++) {
#pragma unroll
        for (int half = 0; half < 2; half++) {
            int oc = wm + i * 16 + (lane >> 2) + half * 8;
            float bb = bias[oc];
#pragma unroll
            for (int j = 0; j < 4; j++) {
                int col = wn + j * 8 + (lane & 3) * 2;
                float v0 = acc[i][j][half * 2 + 0] + bb;
                float v1 = acc[i][j][half * 2 + 1] + bb;
                if (RELU) { v0 = fmaxf(v0, 0.f); v1 = fmaxf(v1, 0.f); }
                if (ROUND) { v0 = to_tf32(v0); v1 = to_tf32(v1); }
                *reinterpret_cast<float2*>(out + (size_t)(b * 64 + oc) * NP + p0 + col) =
                    make_float2(v0, v1);
            }
        }
    }
}

// ---------------- fused IC=3 stage-1 layers (both chains) ----------------
__global__ void k_gemm1x1_pair(const float* __restrict__ W0, const float* __restrict__ b0,
                               const float* __restrict__ W1, const float* __restrict__ b1,
                               const float* __restrict__ pose) {
    const float* __restrict__ W = blockIdx.y ? W1 : W0;
    const float* __restrict__ bias = blockIdx.y ? b1 : b0;
    float* __restrict__ Y = g_a + (size_t)blockIdx.y * 64 * NP;
    const int IC = 3;

    __shared__ float As[16][65];
    __shared__ float Bs[16][64];
    const int tid = threadIdx.x;
    const int tx = tid & 15, ty = tid >> 4;
    const int n0 = blockIdx.x * 64;

    float acc[4][4];
#pragma unroll
    for (int i = 0; i < 4; i++)
#pragma unroll
        for (int j = 0; j < 4; j++) acc[i][j] = 0.f;

#pragma unroll
    for (int i = 0; i < 4; i++) {
        int e = tid + i * 256;
        int k = e & 15, m = e >> 4;
        As[k][m] = (k < IC) ? W[m * IC + k] : 0.f;
    }
#pragma unroll
    for (int i = 0; i < 4; i++) {
        int e = tid + i * 256;
        int n = e & 63, k = e >> 6;
        Bs[k][n] = (k < IC) ? pose[(size_t)k * NP + n0 + n] : 0.f;
    }
    __syncthreads();
#pragma unroll
    for (int k = 0; k < 3; k++) {
        float a[4], b[4];
#pragma unroll
        for (int i = 0; i < 4; i++) a[i] = As[k][ty * 4 + i];
#pragma unroll
        for (int j = 0; j < 4; j++) b[j] = Bs[k][tx * 4 + j];
#pragma unroll
        for (int i = 0; i < 4; i++)
#pragma unroll
            for (int j = 0; j < 4; j++) acc[i][j] += a[i] * b[j];
    }
#pragma unroll
    for (int i = 0; i < 4; i++) {
        float bb = bias[ty * 4 + i];
#pragma unroll
        for (int j = 0; j < 4; j++) {
            float v = fmaxf(acc[i][j] + bb, 0.f);
            Y[(size_t)(ty * 4 + i) * NP + n0 + tx * 4 + j] = to_tf32(v);
        }
    }
}

// ---------------- direct 3x3 conv, pad 1 (layer 3: 64->2) ----------------
template<int SRC, int DST, bool RELU>
__global__ void k_conv3x3(const float* __restrict__ W, const float* __restrict__ bias,
                          int IC, int OC) {
    const float* __restrict__ in = buf_ptr(SRC);
    float* __restrict__ out = buf_ptr(DST);

    __shared__ float s_in[8][34][18];
    __shared__ float s_w[8][16][9];
    const int tx = threadIdx.x, ty = threadIdx.y;
    const int tid = ty * 16 + tx;
    const int x0 = blockIdx.x * 16, y0 = blockIdx.y * 32;
    const int noct = (OC + 15) / 16;
    const int b = blockIdx.z / noct;
    const int oc0 = (blockIdx.z % noct) * 16;

    float acc[16][2];
#pragma unroll
    for (int o = 0; o < 16; o++) { acc[o][0] = 0.f; acc[o][1] = 0.f; }

    for (int ic0 = 0; ic0 < IC; ic0 += 8) {
        for (int i = tid; i < 8 * 34 * 18; i += 256) {
            int ic = i / 612;
            int r = i - ic * 612;
            int yy = r / 18, xx = r - yy * 18;
            int gy = y0 + yy - 1, gx = x0 + xx - 1;
            float v = 0.f;
            if (gy >= 0 && gy < WOUT && gx >= 0 && gx < WOUT)
                v = in[((b * IC + ic0 + ic) * WOUT + gy) * WOUT + gx];
            s_in[ic][yy][xx] = v;
        }
        for (int i = tid; i < 8 * 16 * 9; i += 256) {
            int o = i / 72;
            int r = i - o * 72;
            int ic = r / 9, j = r - ic * 9;
            float v = 0.f;
            if (oc0 + o < OC) v = W[((oc0 + o) * IC + ic0 + ic) * 9 + j];
            s_w[ic][o][j] = v;
        }
        __syncthreads();
#pragma unroll 2
        for (int ic = 0; ic < 8; ic++) {
            float v[4][3];
#pragma unroll
            for (int r = 0; r < 4; r++)
#pragma unroll
                for (int c = 0; c < 3; c++)
                    v[r][c] = s_in[ic][ty * 2 + r][tx + c];
#pragma unroll
            for (int o = 0; o < 16; o++) {
#pragma unroll
                for (int ky = 0; ky < 3; ky++)
#pragma unroll
                    for (int kx = 0; kx < 3; kx++) {
                        float ww = s_w[ic][o][ky * 3 + kx];
                        acc[o][0] += ww * v[ky][kx];
                        acc[o][1] += ww * v[ky + 1][kx];
                    }
            }
        }
        __syncthreads();
    }
#pragma unroll
    for (int o = 0; o < 16; o++) {
        if (oc0 + o < OC) {
            float bb = bias[oc0 + o];
            float* dst = out + ((size_t)(b * OC + oc0 + o) * WOUT + y0 + ty * 2) * WOUT
                         + x0 + tx;
#pragma unroll
            for (int dy = 0; dy < 2; dy++) {
                float v = acc[o][dy] + bb;
                if (RELU) v = fmaxf(v, 0.f);
                dst[dy * WOUT] = v;
            }
        }
    }
}

// ---------------- gather helper ----------------
__device__ __forceinline__ void gather_h(const float* __restrict__ xbc, int iy, int ix,
                                         float* h) {
#pragma unroll
    for (int dy = 0; dy < 3; dy++)
#pragma unroll
        for (int dx = 0; dx < 3; dx++) {
            int yy = iy + dy - 1, xx = ix + dx - 1;
            h[dy * 3 + dx] =
                (yy >= 0 && yy < HIN && xx >= 0 && xx < HIN) ? xbc[yy * HIN + xx] : 0.f;
        }
}

// ---------------- gather + softmax(dw) mean (tf32-rounded output) --------
__global__ void k_mean(const float* __restrict__ x, const int* __restrict__ imY,
                       const int* __restrict__ imX) {
    int idx = blockIdx.x * blockDim.x + threadIdx.x;
    if (idx >= 2 * 64 * NP) return;
    int p = idx % NP;
    int c = (idx / NP) & 63;
    int b = idx / (64 * NP);
    int iy = imY[p], ix = imX[p];
    const float* xbc = x + (b * 64 + c) * (HIN * HIN);
    float h[9];
    gather_h(xbc, iy, ix, h);
    float d[9], mx = -1e30f;
#pragma unroll
    for (int k = 0; k < 9; k++) {
        d[k] = g_dw[(c * 9 + k) * NP + p];
        mx = fmaxf(mx, d[k]);
    }
    float s = 0.f, m = 0.f;
#pragma unroll
    for (int k = 0; k < 9; k++) {
        float e = __expf(d[k] - mx);
        s += e;
        m += h[k] * e;
    }
    g_mean[idx] = to_tf32(m / s);
}

// ---------------- bw + softmax + xa ----------------
__global__ void k_xa(const float* __restrict__ x, const int* __restrict__ imY,
                     const int* __restrict__ imX) {
    int idx = blockIdx.x * blockDim.x + threadIdx.x;
    if (idx >= 2 * 64 * NP) return;
    int p = idx % NP;
    int c = (idx / NP) & 63;
    int b = idx / (64 * NP);
    int iy = imY[p], ix = imX[p];
    const float* xbc = x + (b * 64 + c) * (HIN * HIN);
    float h[9];
    gather_h(xbc, iy, ix, h);
    float m = g_mean[idx];
    float sd = g_sigma[(b * 2 + 0) * NP + p];
    float sr = g_sigma[(b * 2 + 1) * NP + p];
    float bw[9], mx = -1e30f;
#pragma unroll
    for (int k = 0; k < 9; k++) {
        float d = g_dw[(c * 9 + k) * NP + p];
        bw[k] = sd * d + sr * fabsf(h[k] - m);
        mx = fmaxf(mx, bw[k]);
    }
    float s = 0.f, acc = 0.f;
#pragma unroll
    for (int k = 0; k < 9; k++) {
        float e = __expf(bw[k] - mx);
        s += e;
        acc += h[k] * e;
    }
    g_xa[idx] = acc / s;
}

// ---------------- per-pixel 64x3 contraction ----------------
__global__ void k_out(float* __restrict__ out) {
    int idx = blockIdx.x * blockDim.x + threadIdx.x;
    if (idx >= 2 * NP) return;
    int p = idx % NP, b = idx / NP;
    float a0 = 0.f, a1 = 0.f, a2 = 0.f;
#pragma unroll 8
    for (int c = 0; c < 64; c++) {
        float v = g_xa[(b * 64 + c) * NP + p];
        a0 += v * g_pw[(c * 3 + 0) * NP + p];
        a1 += v * g_pw[(c * 3 + 1) * NP + p];
        a2 += v * g_pw[(c * 3 + 2) * NP + p];
    }
    out[(b * 3 + 0) * NP + p] = a0;
    out[(b * 3 + 1) * NP + p] = a1;
    out[(b * 3 + 2) * NP + p] = a2;
}

// ---------------- launch ----------------
extern "C" void kernel_launch(void* const* d_in, const int* in_sizes, int n_in,
                              void* d_out, int out_size) {
    const float* x      = (const float*)d_in[0];
    const float* pose   = (const float*)d_in[1];
    const int*   imY    = (const int*)d_in[2];
    const int*   imX    = (const int*)d_in[3];
    const float* sig_w1 = (const float*)d_in[4];
    const float* sig_b1 = (const float*)d_in[5];
    const float* sig_w2 = (const float*)d_in[6];
    const float* sig_b2 = (const float*)d_in[7];
    const float* sig_w3 = (const float*)d_in[8];
    const float* sig_b3 = (const float*)d_in[9];
    const float* dw_w1  = (const float*)d_in[10];
    const float* dw_b1  = (const float*)d_in[11];
    const float* dw_w2  = (const float*)d_in[12];
    const float* dw_b2  = (const float*)d_in[13];
    const float* dw_w3  = (const float*)d_in[14];
    const float* dw_b3  = (const float*)d_in[15];
    const float* pw_w1  = (const float*)d_in[16];
    const float* pw_b1  = (const float*)d_in[17];
    const float* pw_w2  = (const float*)d_in[18];
    const float* pw_b2  = (const float*)d_in[19];
    const float* pw_w3  = (const float*)d_in[20];
    const float* pw_b3  = (const float*)d_in[21];

    const int NT64 = NP / 64;    // 576
    const int NTG  = NP / 128;   // 288

    // 0,1: weight rounding (fused)
    k_round4<<<896, 256>>>(dw_w2, dw_w3, pw_w2, pw_w3);
    k_round2<<<288, 256>>>(sig_w1, sig_w2);
    // 2: both IC=3 stage-1 layers in one launch (dw -> g_a[0:64), pw -> g_a[64:128))
    k_gemm1x1_pair<<<dim3(NT64, 2), 256>>>(dw_w1, dw_b1, pw_w1, pw_b1, pose);
    // 3,4: stage-2 GEMMs (dw -> g_b[0:256), pw -> g_b[256:512))
    k_gemm_mma<true, true ><<<dim3(NTG, 2), 128>>>(WOFF_DW2, dw_b2, BUF_A, 0,   BUF_B, 0,   256, 64);
    k_gemm_mma<true, true ><<<dim3(NTG, 2), 128>>>(WOFF_PW2, pw_b2, BUF_A, 64,  BUF_B, 256, 256, 64);
    // 5: the big dw3 GEMM (ncu -s 5 lands here)
    k_gemm_mma<false, false><<<dim3(NTG, 5), 128>>>(WOFF_DW3, dw_b3, BUF_B, 0,   BUF_DW, 0, 576, 256);
    // 6: pw3
    k_gemm_mma<false, false><<<dim3(NTG, 2), 128>>>(WOFF_PW3, pw_b3, BUF_B, 256, BUF_PW, 0, 192, 256);

    // gather + softmax(dw)-weighted mean
    k_mean<<<(2 * 64 * NP) / 256, 256>>>(x, imY, imX);

    // sigma net
    k_conv_mma<BUF_MEAN, BUF_S1, true, true ><<<2 * NP / 128, 256>>>(WOFF_SIG1, sig_b1);
    k_conv_mma<BUF_S1, BUF_S2, true, false><<<2 * NP / 128, 256>>>(WOFF_SIG2, sig_b2);
    k_conv3x3<BUF_S2, BUF_SIGMA, false><<<dim3(12, 6, 2 * 1), dim3(16, 16)>>>(sig_w3, sig_b3, 64, 2);

    // bw + softmax + xa
    k_xa<<<(2 * 64 * NP) / 256, 256>>>(x, imY, imX);

    // out[b,o,p] = sum_c xa[b,c,p] * pw[c,o,p]
    k_out<<<(2 * NP + 255) / 256, 256>>>((float*)d_out);
}